// round 1
// baseline (speedup 1.0000x reference)
#include <cuda_runtime.h>
#include <math.h>

#define Bd 2
#define Td 2048
#define Hd 1024
#define Ld 256
#define Fd 2048
#define Ed 7
#define BTd (Bd*Td)

// ---------------- scratch (device globals; no allocation) ----------------
__device__ float g_h[BTd*Hd];
__device__ float g_kvlat[BTd*Ld];
__device__ float g_qlat[BTd*Ld];
__device__ float g_v[BTd*Hd];
__device__ float g_q[BTd*Hd];
__device__ float g_k[BTd*Hd];
__device__ float g_scores[(size_t)Bd*Td*Td];
__device__ float g_y[BTd*Hd];
__device__ float g_x1[BTd*Hd];
__device__ float g_h2[BTd*Hd];
__device__ float g_gbuf[BTd*Fd];
__device__ float g_ubuf[BTd*Fd];
__device__ float g_shb[BTd*Hd];
__device__ float g_r0[BTd*Hd];
__device__ float g_r1[BTd*Hd];
__device__ int   g_cnt[Ed];
__device__ int   g_gidx[Ed*BTd];
__device__ float g_gwt[Ed*BTd];
__device__ int   g_gslot[Ed*BTd];

// ---------------- block reduce ----------------
template<bool DOMAX>
__device__ __forceinline__ float blockReduce(float v) {
    __shared__ float sh[8];
    __shared__ float res;
    int lane = threadIdx.x & 31, w = threadIdx.x >> 5;
    #pragma unroll
    for (int o = 16; o; o >>= 1) {
        float t = __shfl_xor_sync(0xffffffffu, v, o);
        v = DOMAX ? fmaxf(v, t) : v + t;
    }
    if (lane == 0) sh[w] = v;
    __syncthreads();
    if (w == 0) {
        v = (lane < (int)(blockDim.x >> 5)) ? sh[lane] : (DOMAX ? -3.4e38f : 0.f);
        #pragma unroll
        for (int o = 4; o; o >>= 1) {
            float t = __shfl_xor_sync(0xffffffffu, v, o);
            v = DOMAX ? fmaxf(v, t) : v + t;
        }
        if (lane == 0) res = v;
    }
    __syncthreads();
    return res;
}

// ---------------- layernorm ----------------
__global__ void ln_kernel(const float* __restrict__ x, const float* __restrict__ w,
                          float* __restrict__ out) {
    int row = blockIdx.x;
    const float* xr = x + (size_t)row * Hd;
    int t = threadIdx.x;
    float v[4];
    float s = 0.f;
    #pragma unroll
    for (int i = 0; i < 4; i++) { v[i] = xr[t + 256*i]; s += v[i]; }
    s = blockReduce<false>(s);
    float mu = s * (1.f / Hd);
    float q = 0.f;
    #pragma unroll
    for (int i = 0; i < 4; i++) { float d = v[i] - mu; q += d * d; }
    q = blockReduce<false>(q);
    float rs = rsqrtf(q * (1.f / Hd) + 1e-5f);
    float* o = out + (size_t)row * Hd;
    #pragma unroll
    for (int i = 0; i < 4; i++) o[t + 256*i] = (v[i] - mu) * rs * w[t + 256*i];
}

// ---------------- rope (in-place, pairwise so no race) ----------------
__global__ void rope_kernel(float* __restrict__ q, float* __restrict__ k) {
    int row = blockIdx.x;
    int t = row % Td;
    size_t base = (size_t)row * Hd;
    #pragma unroll
    for (int it = 0; it < 2; it++) {
        int p = threadIdx.x + 256 * it;   // 0..511
        double invf = exp(-(double)(2 * p) / 1024.0 * 9.210340371976184);
        float f = (float)t * (float)invf;
        float c = cosf(f), s = sinf(f);
        float q1 = q[base + p], q2 = q[base + p + 512];
        q[base + p]       = q1 * c - q2 * s;
        q[base + p + 512] = q2 * c + q1 * s;
        float k1 = k[base + p], k2 = k[base + p + 512];
        k[base + p]       = k1 * c - k2 * s;
        k[base + p + 512] = k2 * c + k1 * s;
    }
}

// ---------------- softmax (causal) ----------------
__global__ void softmax_kernel(float* __restrict__ sc) {
    int b = blockIdx.y, i = blockIdx.x;
    float* row = sc + ((size_t)b * Td + i) * Td;
    int t = threadIdx.x;
    int n = i + 1;
    float mx = -3.4e38f;
    for (int j = t; j < n; j += 256) mx = fmaxf(mx, row[j]);
    mx = blockReduce<true>(mx);
    float s = 0.f;
    for (int j = t; j < n; j += 256) s += expf(row[j] - mx);
    s = blockReduce<false>(s);
    float inv = 1.f / s;
    for (int j = t; j < Td; j += 256)
        row[j] = (j < n) ? expf(row[j] - mx) * inv : 0.f;
}

// ---------------- router + top2 gather lists ----------------
__global__ void zero_cnt_kernel() {
    if (threadIdx.x < Ed) g_cnt[threadIdx.x] = 0;
}

__global__ void router_kernel(const float* __restrict__ h2, const float* __restrict__ rw,
                              const float* __restrict__ rb) {
    int m = blockIdx.x;
    int w = threadIdx.x >> 5, lane = threadIdx.x & 31;
    __shared__ float probs[Ed];
    if (w < Ed) {
        const float* hv = h2 + (size_t)m * Hd;
        const float* wv = rw + (size_t)w * Hd;
        float s = 0.f;
        for (int j = lane; j < Hd; j += 32) s += hv[j] * wv[j];
        #pragma unroll
        for (int o = 16; o; o >>= 1) s += __shfl_xor_sync(0xffffffffu, s, o);
        if (lane == 0) probs[w] = 1.f / (1.f + expf(-(s + rb[w])));
    }
    __syncthreads();
    if (threadIdx.x == 0) {
        int e0 = 0; float p0 = probs[0];
        for (int e = 1; e < Ed; e++) if (probs[e] > p0) { p0 = probs[e]; e0 = e; }
        int e1 = -1; float p1 = -3.4e38f;
        for (int e = 0; e < Ed; e++) if (e != e0 && probs[e] > p1) { p1 = probs[e]; e1 = e; }
        int pos = atomicAdd(&g_cnt[e0], 1);
        g_gidx[e0*BTd + pos] = m; g_gwt[e0*BTd + pos] = p0; g_gslot[e0*BTd + pos] = 0;
        pos = atomicAdd(&g_cnt[e1], 1);
        g_gidx[e1*BTd + pos] = m; g_gwt[e1*BTd + pos] = p1; g_gslot[e1*BTd + pos] = 1;
    }
}

// ---------------- generic 128x128x8 tiled GEMM, C = A @ B^T (or A @ B) ----
// MODE 0: C=v   1: C=silu(v)   2: C=v*aux   3: C=v+aux
//      4: scatter w*v to (r0|r1)[gidx[gm]]   5: C=v*scale, causal tile skip
template<int MODE, bool BTRANS, bool GATHER>
__global__ void __launch_bounds__(256) gemm_k(
    const float* __restrict__ A, const float* __restrict__ Bm,
    float* __restrict__ C, float* __restrict__ C2,
    const float* __restrict__ aux,
    int M, int N, int K, int lda, int ldb, int ldc,
    const int* __restrict__ gcount, const int* __restrict__ gidx,
    const float* __restrict__ gwt, const int* __restrict__ gslot)
{
    const int bm = blockIdx.y * 128;
    const int bn = blockIdx.x * 128;
    if (MODE == 5 && bn > bm + 127) return;   // fully-masked causal tile
    int Meff = M;
    if (gcount) Meff = *gcount;
    if (bm >= Meff) return;

    __shared__ float As[8][132];
    __shared__ float Bs[8][132];

    const int tid = threadIdx.x;
    const int lr = tid >> 1;
    const int lc = (tid & 1) * 4;
    const int ty = tid >> 4, tx = tid & 15;

    float acc[8][8];
    #pragma unroll
    for (int i = 0; i < 8; i++)
        #pragma unroll
        for (int j = 0; j < 8; j++) acc[i][j] = 0.f;

    int arow = bm + lr;
    bool aval = arow < Meff;
    int asrc = 0;
    if (aval) asrc = GATHER ? gidx[arow] : arow;
    const float* Ap = A + (size_t)asrc * lda + lc;

    const float* Bp;
    int bkk = 0, bnn = 0;
    if (BTRANS) {
        Bp = Bm + (size_t)(bn + lr) * ldb + lc;
    } else {
        bkk = tid >> 5;
        bnn = (tid & 31) * 4;
        Bp = Bm + (size_t)bkk * ldb + bn + bnn;
    }

    for (int kt = 0; kt < K; kt += 8) {
        float4 av = aval ? *(const float4*)(Ap + kt) : make_float4(0.f,0.f,0.f,0.f);
        As[lc+0][lr] = av.x; As[lc+1][lr] = av.y; As[lc+2][lr] = av.z; As[lc+3][lr] = av.w;
        if (BTRANS) {
            float4 bv = *(const float4*)(Bp + kt);
            Bs[lc+0][lr] = bv.x; Bs[lc+1][lr] = bv.y; Bs[lc+2][lr] = bv.z; Bs[lc+3][lr] = bv.w;
        } else {
            float4 bv = *(const float4*)(Bp + (size_t)kt * ldb);
            Bs[bkk][bnn+0] = bv.x; Bs[bkk][bnn+1] = bv.y; Bs[bkk][bnn+2] = bv.z; Bs[bkk][bnn+3] = bv.w;
        }
        __syncthreads();
        #pragma unroll
        for (int kk = 0; kk < 8; kk++) {
            float a[8], b[8];
            #pragma unroll
            for (int i = 0; i < 8; i++) a[i] = As[kk][ty*8 + i];
            #pragma unroll
            for (int j = 0; j < 8; j++) b[j] = Bs[kk][tx*8 + j];
            #pragma unroll
            for (int i = 0; i < 8; i++)
                #pragma unroll
                for (int j = 0; j < 8; j++) acc[i][j] += a[i] * b[j];
        }
        __syncthreads();
    }

    #pragma unroll
    for (int i = 0; i < 8; i++) {
        int gm = bm + ty*8 + i;
        if (gm >= Meff) continue;
        int trow = 0; float wgt = 0.f; float* Ct = C;
        if (MODE == 4) { trow = gidx[gm]; wgt = gwt[gm]; Ct = gslot[gm] ? C2 : C; }
        #pragma unroll
        for (int j = 0; j < 8; j++) {
            int gn = bn + tx*8 + j;
            float v = acc[i][j];
            size_t o = (size_t)gm * ldc + gn;
            if (MODE == 0)      C[o] = v;
            else if (MODE == 1) C[o] = v / (1.f + expf(-v));
            else if (MODE == 2) C[o] = v * aux[o];
            else if (MODE == 3) C[o] = v + aux[o];
            else if (MODE == 4) Ct[(size_t)trow * ldc + gn] = wgt * v;
            else if (MODE == 5) C[o] = v * 0.03125f;   // 1/sqrt(1024)
        }
    }
}

// ---------------- final add ----------------
__global__ void final_add_kernel(const float* __restrict__ a, const float* __restrict__ b,
                                 const float* __restrict__ c, const float* __restrict__ d,
                                 float* __restrict__ out) {
    size_t i = (size_t)blockIdx.x * blockDim.x + threadIdx.x;
    out[i] = a[i] + b[i] + c[i] + d[i];
}

// ---------------- launch ----------------
extern "C" void kernel_launch(void* const* d_in, const int* in_sizes, int n_in,
                              void* d_out, int out_size) {
    (void)in_sizes; (void)n_in; (void)out_size;
    const float* x         = (const float*)d_in[0];
    const float* ln1w      = (const float*)d_in[1];
    const float* ln2w      = (const float*)d_in[2];
    const float* kv_proj_d = (const float*)d_in[3];
    const float* q_proj_d  = (const float*)d_in[4];
    const float* v_proj_u  = (const float*)d_in[7];
    const float* rope_k    = (const float*)d_in[8];
    const float* rope_q    = (const float*)d_in[9];
    const float* o_proj    = (const float*)d_in[10];
    const float* router_w  = (const float*)d_in[11];
    const float* router_b  = (const float*)d_in[12];
    const float* sh_gate   = (const float*)d_in[13];
    const float* sh_up     = (const float*)d_in[14];
    const float* sh_down   = (const float*)d_in[15];
    const float* ex_gate   = (const float*)d_in[16];
    const float* ex_up     = (const float*)d_in[17];
    const float* ex_down   = (const float*)d_in[18];
    float* out = (float*)d_out;

    float *h,*kvlat,*qlat,*v,*q,*k,*scores,*y,*x1,*h2,*gbuf,*ubuf,*shb,*r0,*r1,*gwt;
    int *cnt,*gidx,*gslot;
    cudaGetSymbolAddress((void**)&h, g_h);
    cudaGetSymbolAddress((void**)&kvlat, g_kvlat);
    cudaGetSymbolAddress((void**)&qlat, g_qlat);
    cudaGetSymbolAddress((void**)&v, g_v);
    cudaGetSymbolAddress((void**)&q, g_q);
    cudaGetSymbolAddress((void**)&k, g_k);
    cudaGetSymbolAddress((void**)&scores, g_scores);
    cudaGetSymbolAddress((void**)&y, g_y);
    cudaGetSymbolAddress((void**)&x1, g_x1);
    cudaGetSymbolAddress((void**)&h2, g_h2);
    cudaGetSymbolAddress((void**)&gbuf, g_gbuf);
    cudaGetSymbolAddress((void**)&ubuf, g_ubuf);
    cudaGetSymbolAddress((void**)&shb, g_shb);
    cudaGetSymbolAddress((void**)&r0, g_r0);
    cudaGetSymbolAddress((void**)&r1, g_r1);
    cudaGetSymbolAddress((void**)&cnt, g_cnt);
    cudaGetSymbolAddress((void**)&gidx, g_gidx);
    cudaGetSymbolAddress((void**)&gwt, g_gwt);
    cudaGetSymbolAddress((void**)&gslot, g_gslot);

    zero_cnt_kernel<<<1, 32>>>();

    // ---- attention ----
    ln_kernel<<<BTd, 256>>>(x, ln1w, h);

    // qlat = h @ q_proj_d.T   [BT,L]
    gemm_k<0,true,false><<<dim3(Ld/128, BTd/128), 256>>>(h, q_proj_d, qlat, nullptr, nullptr,
        BTd, Ld, Hd, Hd, Hd, Ld, nullptr, nullptr, nullptr, nullptr);
    // kvlat = h @ kv_proj_d.T
    gemm_k<0,true,false><<<dim3(Ld/128, BTd/128), 256>>>(h, kv_proj_d, kvlat, nullptr, nullptr,
        BTd, Ld, Hd, Hd, Hd, Ld, nullptr, nullptr, nullptr, nullptr);
    // v = kvlat @ v_proj_u.T   [BT,H]
    gemm_k<0,true,false><<<dim3(Hd/128, BTd/128), 256>>>(kvlat, v_proj_u, v, nullptr, nullptr,
        BTd, Hd, Ld, Ld, Ld, Hd, nullptr, nullptr, nullptr, nullptr);
    // q_r = qlat @ rope_q.T
    gemm_k<0,true,false><<<dim3(Hd/128, BTd/128), 256>>>(qlat, rope_q, q, nullptr, nullptr,
        BTd, Hd, Ld, Ld, Ld, Hd, nullptr, nullptr, nullptr, nullptr);
    // k_r = h @ rope_k.T
    gemm_k<0,true,false><<<dim3(Hd/128, BTd/128), 256>>>(h, rope_k, k, nullptr, nullptr,
        BTd, Hd, Hd, Hd, Hd, Hd, nullptr, nullptr, nullptr, nullptr);

    rope_kernel<<<BTd, 256>>>(q, k);

    for (int b = 0; b < Bd; b++) {
        gemm_k<5,true,false><<<dim3(Td/128, Td/128), 256>>>(
            q + (size_t)b*Td*Hd, k + (size_t)b*Td*Hd, scores + (size_t)b*Td*Td,
            nullptr, nullptr, Td, Td, Hd, Hd, Hd, Td, nullptr, nullptr, nullptr, nullptr);
    }
    softmax_kernel<<<dim3(Td, Bd), 256>>>(scores);
    for (int b = 0; b < Bd; b++) {
        gemm_k<0,false,false><<<dim3(Hd/128, Td/128), 256>>>(
            scores + (size_t)b*Td*Td, v + (size_t)b*Td*Hd, y + (size_t)b*Td*Hd,
            nullptr, nullptr, Td, Hd, Td, Td, Hd, Hd, nullptr, nullptr, nullptr, nullptr);
    }
    // x1 = x + y @ o_proj.T
    gemm_k<3,true,false><<<dim3(Hd/128, BTd/128), 256>>>(y, o_proj, x1, nullptr, x,
        BTd, Hd, Hd, Hd, Hd, Hd, nullptr, nullptr, nullptr, nullptr);

    // ---- MoE ----
    ln_kernel<<<BTd, 256>>>(x1, ln2w, h2);
    router_kernel<<<BTd, 256>>>(h2, router_w, router_b);

    // shared expert
    gemm_k<1,true,false><<<dim3(Fd/128, BTd/128), 256>>>(h2, sh_gate, gbuf, nullptr, nullptr,
        BTd, Fd, Hd, Hd, Hd, Fd, nullptr, nullptr, nullptr, nullptr);
    gemm_k<2,true,false><<<dim3(Fd/128, BTd/128), 256>>>(h2, sh_up, ubuf, nullptr, gbuf,
        BTd, Fd, Hd, Hd, Hd, Fd, nullptr, nullptr, nullptr, nullptr);
    gemm_k<0,true,false><<<dim3(Hd/128, BTd/128), 256>>>(ubuf, sh_down, shb, nullptr, nullptr,
        BTd, Hd, Fd, Fd, Fd, Hd, nullptr, nullptr, nullptr, nullptr);

    // routed experts (gathered top-2)
    for (int e = 0; e < Ed; e++) {
        const float* wg = ex_gate + (size_t)e * Fd * Hd;
        const float* wu = ex_up   + (size_t)e * Fd * Hd;
        const float* wd = ex_down + (size_t)e * Hd * Fd;
        gemm_k<1,true,true><<<dim3(Fd/128, BTd/128), 256>>>(h2, wg, gbuf, nullptr, nullptr,
            BTd, Fd, Hd, Hd, Hd, Fd, cnt + e, gidx + e*BTd, nullptr, nullptr);
        gemm_k<2,true,true><<<dim3(Fd/128, BTd/128), 256>>>(h2, wu, ubuf, nullptr, gbuf,
            BTd, Fd, Hd, Hd, Hd, Fd, cnt + e, gidx + e*BTd, nullptr, nullptr);
        gemm_k<4,true,false><<<dim3(Hd/128, BTd/128), 256>>>(ubuf, wd, r0, r1, nullptr,
            BTd, Hd, Fd, Fd, Fd, Hd, cnt + e, gidx + e*BTd, gwt + e*BTd, gslot + e*BTd);
    }

    final_add_kernel<<<(BTd * Hd) / 256, 256>>>(x1, shb, r0, r1, out);
}

// round 2
// speedup vs baseline: 2.4491x; 2.4491x over previous
#include <cuda_runtime.h>
#include <math.h>

#define Bd 2
#define Td 2048
#define Hd 1024
#define Ld 256
#define Fd 2048
#define Ed 7
#define BTd (Bd*Td)

// ---------------- scratch (device globals; no allocation) ----------------
__device__ float g_h[BTd*Hd];
__device__ float g_kvlat[BTd*Ld];
__device__ float g_qlat[BTd*Ld];
__device__ float g_v[BTd*Hd];
__device__ float g_q[BTd*Hd];
__device__ float g_k[BTd*Hd];
__device__ float g_scores[(size_t)Bd*Td*Td];
__device__ float g_y[BTd*Hd];
__device__ float g_x1[BTd*Hd];
__device__ float g_h2[BTd*Hd];
__device__ float g_gbuf[BTd*Fd];
__device__ float g_ubuf[BTd*Fd];
__device__ float g_shb[BTd*Hd];
__device__ float g_r0[BTd*Hd];
__device__ float g_r1[BTd*Hd];
__device__ int   g_cnt[Ed];
__device__ int   g_gidx[Ed*BTd];
__device__ float g_gwt[Ed*BTd];
__device__ int   g_gslot[Ed*BTd];

// ---------------- block reduce ----------------
template<bool DOMAX>
__device__ __forceinline__ float blockReduce(float v) {
    __shared__ float sh[8];
    __shared__ float res;
    int lane = threadIdx.x & 31, w = threadIdx.x >> 5;
    #pragma unroll
    for (int o = 16; o; o >>= 1) {
        float t = __shfl_xor_sync(0xffffffffu, v, o);
        v = DOMAX ? fmaxf(v, t) : v + t;
    }
    if (lane == 0) sh[w] = v;
    __syncthreads();
    if (w == 0) {
        v = (lane < (int)(blockDim.x >> 5)) ? sh[lane] : (DOMAX ? -3.4e38f : 0.f);
        #pragma unroll
        for (int o = 4; o; o >>= 1) {
            float t = __shfl_xor_sync(0xffffffffu, v, o);
            v = DOMAX ? fmaxf(v, t) : v + t;
        }
        if (lane == 0) res = v;
    }
    __syncthreads();
    return res;
}

// ---------------- layernorm ----------------
__global__ void ln_kernel(const float* __restrict__ x, const float* __restrict__ w,
                          float* __restrict__ out) {
    int row = blockIdx.x;
    const float* xr = x + (size_t)row * Hd;
    int t = threadIdx.x;
    float v[4];
    float s = 0.f;
    #pragma unroll
    for (int i = 0; i < 4; i++) { v[i] = xr[t + 256*i]; s += v[i]; }
    s = blockReduce<false>(s);
    float mu = s * (1.f / Hd);
    float q = 0.f;
    #pragma unroll
    for (int i = 0; i < 4; i++) { float d = v[i] - mu; q += d * d; }
    q = blockReduce<false>(q);
    float rs = rsqrtf(q * (1.f / Hd) + 1e-5f);
    float* o = out + (size_t)row * Hd;
    #pragma unroll
    for (int i = 0; i < 4; i++) o[t + 256*i] = (v[i] - mu) * rs * w[t + 256*i];
}

// ---------------- rope (in-place, pairwise so no race) ----------------
__global__ void rope_kernel(float* __restrict__ q, float* __restrict__ k) {
    int row = blockIdx.x;
    int t = row % Td;
    size_t base = (size_t)row * Hd;
    #pragma unroll
    for (int it = 0; it < 2; it++) {
        int p = threadIdx.x + 256 * it;   // 0..511
        double invf = exp(-(double)(2 * p) / 1024.0 * 9.210340371976184);
        float f = (float)t * (float)invf;
        float c = cosf(f), s = sinf(f);
        float q1 = q[base + p], q2 = q[base + p + 512];
        q[base + p]       = q1 * c - q2 * s;
        q[base + p + 512] = q2 * c + q1 * s;
        float k1 = k[base + p], k2 = k[base + p + 512];
        k[base + p]       = k1 * c - k2 * s;
        k[base + p + 512] = k2 * c + k1 * s;
    }
}

// ---------------- softmax (causal) ----------------
__global__ void softmax_kernel(float* __restrict__ sc) {
    int b = blockIdx.y, i = blockIdx.x;
    float* row = sc + ((size_t)b * Td + i) * Td;
    int t = threadIdx.x;
    int n = i + 1;
    float mx = -3.4e38f;
    for (int j = t; j < n; j += 256) mx = fmaxf(mx, row[j]);
    mx = blockReduce<true>(mx);
    float s = 0.f;
    for (int j = t; j < n; j += 256) s += expf(row[j] - mx);
    s = blockReduce<false>(s);
    float inv = 1.f / s;
    for (int j = t; j < Td; j += 256)
        row[j] = (j < n) ? expf(row[j] - mx) * inv : 0.f;
}

// ---------------- router + top2 gather lists ----------------
__global__ void zero_cnt_kernel() {
    if (threadIdx.x < Ed) g_cnt[threadIdx.x] = 0;
}

__global__ void router_kernel(const float* __restrict__ h2, const float* __restrict__ rw,
                              const float* __restrict__ rb) {
    int m = blockIdx.x;
    int w = threadIdx.x >> 5, lane = threadIdx.x & 31;
    __shared__ float probs[Ed];
    if (w < Ed) {
        const float* hv = h2 + (size_t)m * Hd;
        const float* wv = rw + (size_t)w * Hd;
        float s = 0.f;
        for (int j = lane; j < Hd; j += 32) s += hv[j] * wv[j];
        #pragma unroll
        for (int o = 16; o; o >>= 1) s += __shfl_xor_sync(0xffffffffu, s, o);
        if (lane == 0) probs[w] = 1.f / (1.f + expf(-(s + rb[w])));
    }
    __syncthreads();
    if (threadIdx.x == 0) {
        int e0 = 0; float p0 = probs[0];
        for (int e = 1; e < Ed; e++) if (probs[e] > p0) { p0 = probs[e]; e0 = e; }
        int e1 = -1; float p1 = -3.4e38f;
        for (int e = 0; e < Ed; e++) if (e != e0 && probs[e] > p1) { p1 = probs[e]; e1 = e; }
        int pos = atomicAdd(&g_cnt[e0], 1);
        g_gidx[e0*BTd + pos] = m; g_gwt[e0*BTd + pos] = p0; g_gslot[e0*BTd + pos] = 0;
        pos = atomicAdd(&g_cnt[e1], 1);
        g_gidx[e1*BTd + pos] = m; g_gwt[e1*BTd + pos] = p1; g_gslot[e1*BTd + pos] = 1;
    }
}

// ---------------- tf32 helpers ----------------
__device__ __forceinline__ unsigned f2tf(float f) {
    unsigned u;
    asm("cvt.rna.tf32.f32 %0, %1;" : "=r"(u) : "f"(f));
    return u;
}

// XOR swizzle: conflict-free for both smem stores and mma fragment loads
__device__ __forceinline__ int swz(int m, int k) {
    return m * 16 + (k ^ (((m >> 1) & 3) << 2) ^ (((m >> 3) & 1) << 1));
}

__device__ __forceinline__ void mma_tf32(float* d, const unsigned* a, const unsigned* b) {
    asm volatile(
        "mma.sync.aligned.m16n8k8.row.col.f32.tf32.tf32.f32 "
        "{%0,%1,%2,%3}, {%4,%5,%6,%7}, {%8,%9}, {%0,%1,%2,%3};"
        : "+f"(d[0]), "+f"(d[1]), "+f"(d[2]), "+f"(d[3])
        : "r"(a[0]), "r"(a[1]), "r"(a[2]), "r"(a[3]), "r"(b[0]), "r"(b[1]));
}

// ---------------- tensor-core tiled GEMM, 128x128 tile, KT=16 ----------
// MODE 0: C=v   1: C=silu(v)   2: C=v*aux   3: C=v+aux
//      4: scatter w*v to (C|C2)[gidx[gm]]   5: C=v*scale, causal tile skip
// BTRANS: C = A @ B^T (B row-major [N,K]); else C = A @ B (B row-major [K,N])
template<int MODE, bool BTRANS, bool GATHER>
__global__ void __launch_bounds__(256) gemm_mma(
    const float* __restrict__ A, const float* __restrict__ Bm,
    float* __restrict__ C, float* __restrict__ C2,
    const float* __restrict__ aux,
    int M, int N, int K, int lda, int ldb, int ldc,
    const int* __restrict__ gcount, const int* __restrict__ gidx,
    const float* __restrict__ gwt, const int* __restrict__ gslot)
{
    const int bm = blockIdx.y * 128;
    const int bn = blockIdx.x * 128;
    if (MODE == 5 && bn > bm + 127) return;   // fully-masked causal tile
    int Meff = M;
    if (gcount) Meff = *gcount;
    if (bm >= Meff) return;

    __shared__ unsigned As[128 * 16];
    __shared__ unsigned Bs[128 * 16];

    const int tid = threadIdx.x;
    const int lane = tid & 31, wid = tid >> 5;
    const int wm = wid & 1, wn = wid >> 1;     // 2 x 4 warp grid
    const int gid = lane >> 2, tig = lane & 3;

    // --- A loader: 2 threads per row, 8 floats each ---
    const int arow = tid >> 1;                 // 0..127
    const int akoff = (tid & 1) * 8;           // 0 or 8
    const int am = bm + arow;
    const bool aval = am < Meff;
    int asrc = 0;
    if (aval) asrc = GATHER ? gidx[am] : am;
    const float* Ap = A + (size_t)asrc * lda + akoff;

    // --- B loader ---
    const float* Bp;
    int brow = 0, bkoff = 0, bk = 0, bn8 = 0;
    if (BTRANS) {
        brow = tid >> 1; bkoff = (tid & 1) * 8;
        Bp = Bm + (size_t)(bn + brow) * ldb + bkoff;
    } else {
        bk = tid >> 4; bn8 = (tid & 15) * 8;
        Bp = Bm + (size_t)bk * ldb + bn + bn8;
    }

    float acc[4][4][4];
    #pragma unroll
    for (int i = 0; i < 4; i++)
        #pragma unroll
        for (int j = 0; j < 4; j++)
            #pragma unroll
            for (int l = 0; l < 4; l++) acc[i][j][l] = 0.f;

    float4 a0_0, a0_1, b0_0, b0_1;   // stage 0 prefetch
    float4 a1_0, a1_1, b1_0, b1_1;   // stage 1 prefetch
    const float4 Z = make_float4(0.f, 0.f, 0.f, 0.f);

    // prologue: load tiles kt=0 and kt=16
    a0_0 = aval ? *(const float4*)(Ap)     : Z;
    a0_1 = aval ? *(const float4*)(Ap + 4) : Z;
    if (BTRANS) { b0_0 = *(const float4*)(Bp); b0_1 = *(const float4*)(Bp + 4); }
    else        { b0_0 = *(const float4*)(Bp); b0_1 = *(const float4*)(Bp + 4); }

    a1_0 = aval ? *(const float4*)(Ap + 16)     : Z;
    a1_1 = aval ? *(const float4*)(Ap + 16 + 4) : Z;
    if (BTRANS) { b1_0 = *(const float4*)(Bp + 16); b1_1 = *(const float4*)(Bp + 16 + 4); }
    else        { b1_0 = *(const float4*)(Bp + (size_t)16 * ldb);
                  b1_1 = *(const float4*)(Bp + (size_t)16 * ldb + 4); }

    for (int kt = 0; kt < K; kt += 16) {
        // ---- store stage-0 prefetch to smem (cvt to tf32, swizzled) ----
        {
            float av[8] = {a0_0.x, a0_0.y, a0_0.z, a0_0.w, a0_1.x, a0_1.y, a0_1.z, a0_1.w};
            #pragma unroll
            for (int j = 0; j < 8; j++) As[swz(arow, akoff + j)] = f2tf(av[j]);
            float bv[8] = {b0_0.x, b0_0.y, b0_0.z, b0_0.w, b0_1.x, b0_1.y, b0_1.z, b0_1.w};
            if (BTRANS) {
                #pragma unroll
                for (int j = 0; j < 8; j++) Bs[swz(brow, bkoff + j)] = f2tf(bv[j]);
            } else {
                #pragma unroll
                for (int j = 0; j < 8; j++) Bs[swz(bn8 + j, bk)] = f2tf(bv[j]);
            }
        }
        __syncthreads();

        // ---- rotate prefetch stages, issue load for kt+32 ----
        a0_0 = a1_0; a0_1 = a1_1; b0_0 = b1_0; b0_1 = b1_1;
        if (kt + 32 < K) {
            const int kn = kt + 32;
            a1_0 = aval ? *(const float4*)(Ap + kn)     : Z;
            a1_1 = aval ? *(const float4*)(Ap + kn + 4) : Z;
            if (BTRANS) { b1_0 = *(const float4*)(Bp + kn); b1_1 = *(const float4*)(Bp + kn + 4); }
            else        { b1_0 = *(const float4*)(Bp + (size_t)kn * ldb);
                          b1_1 = *(const float4*)(Bp + (size_t)kn * ldb + 4); }
        }

        // ---- compute: 2 x k8 steps ----
        #pragma unroll
        for (int k8 = 0; k8 < 16; k8 += 8) {
            unsigned af[4][4], bf[4][2];
            #pragma unroll
            for (int mt = 0; mt < 4; mt++) {
                int r = wm * 64 + mt * 16 + gid;
                af[mt][0] = As[swz(r,     k8 + tig)];
                af[mt][1] = As[swz(r + 8, k8 + tig)];
                af[mt][2] = As[swz(r,     k8 + tig + 4)];
                af[mt][3] = As[swz(r + 8, k8 + tig + 4)];
            }
            #pragma unroll
            for (int nt = 0; nt < 4; nt++) {
                int c = wn * 32 + nt * 8 + gid;
                bf[nt][0] = Bs[swz(c, k8 + tig)];
                bf[nt][1] = Bs[swz(c, k8 + tig + 4)];
            }
            #pragma unroll
            for (int mt = 0; mt < 4; mt++)
                #pragma unroll
                for (int nt = 0; nt < 4; nt++)
                    mma_tf32(acc[mt][nt], af[mt], bf[nt]);
        }
        __syncthreads();
    }

    // ---- epilogue ----
    #pragma unroll
    for (int mt = 0; mt < 4; mt++) {
        #pragma unroll
        for (int i2 = 0; i2 < 2; i2++) {
            int gm = bm + wm * 64 + mt * 16 + gid + i2 * 8;
            if (gm >= Meff) continue;
            int trow = 0; float wgt = 0.f; float* Ct = C;
            if (MODE == 4) { trow = gidx[gm]; wgt = gwt[gm]; Ct = gslot[gm] ? C2 : C; }
            #pragma unroll
            for (int nt = 0; nt < 4; nt++) {
                #pragma unroll
                for (int j2 = 0; j2 < 2; j2++) {
                    int gn = bn + wn * 32 + nt * 8 + tig * 2 + j2;
                    float v = acc[mt][nt][i2 * 2 + j2];
                    size_t o = (size_t)gm * ldc + gn;
                    if (MODE == 0)      C[o] = v;
                    else if (MODE == 1) C[o] = v / (1.f + expf(-v));
                    else if (MODE == 2) C[o] = v * aux[o];
                    else if (MODE == 3) C[o] = v + aux[o];
                    else if (MODE == 4) Ct[(size_t)trow * ldc + gn] = wgt * v;
                    else if (MODE == 5) C[o] = v * 0.03125f;   // 1/sqrt(1024)
                }
            }
        }
    }
}

// ---------------- final add ----------------
__global__ void final_add_kernel(const float* __restrict__ a, const float* __restrict__ b,
                                 const float* __restrict__ c, const float* __restrict__ d,
                                 float* __restrict__ out) {
    size_t i = (size_t)blockIdx.x * blockDim.x + threadIdx.x;
    out[i] = a[i] + b[i] + c[i] + d[i];
}

// ---------------- launch ----------------
extern "C" void kernel_launch(void* const* d_in, const int* in_sizes, int n_in,
                              void* d_out, int out_size) {
    (void)in_sizes; (void)n_in; (void)out_size;
    const float* x         = (const float*)d_in[0];
    const float* ln1w      = (const float*)d_in[1];
    const float* ln2w      = (const float*)d_in[2];
    const float* kv_proj_d = (const float*)d_in[3];
    const float* q_proj_d  = (const float*)d_in[4];
    const float* v_proj_u  = (const float*)d_in[7];
    const float* rope_k    = (const float*)d_in[8];
    const float* rope_q    = (const float*)d_in[9];
    const float* o_proj    = (const float*)d_in[10];
    const float* router_w  = (const float*)d_in[11];
    const float* router_b  = (const float*)d_in[12];
    const float* sh_gate   = (const float*)d_in[13];
    const float* sh_up     = (const float*)d_in[14];
    const float* sh_down   = (const float*)d_in[15];
    const float* ex_gate   = (const float*)d_in[16];
    const float* ex_up     = (const float*)d_in[17];
    const float* ex_down   = (const float*)d_in[18];
    float* out = (float*)d_out;

    float *h,*kvlat,*qlat,*v,*q,*k,*scores,*y,*x1,*h2,*gbuf,*ubuf,*shb,*r0,*r1,*gwt;
    int *cnt,*gidx,*gslot;
    cudaGetSymbolAddress((void**)&h, g_h);
    cudaGetSymbolAddress((void**)&kvlat, g_kvlat);
    cudaGetSymbolAddress((void**)&qlat, g_qlat);
    cudaGetSymbolAddress((void**)&v, g_v);
    cudaGetSymbolAddress((void**)&q, g_q);
    cudaGetSymbolAddress((void**)&k, g_k);
    cudaGetSymbolAddress((void**)&scores, g_scores);
    cudaGetSymbolAddress((void**)&y, g_y);
    cudaGetSymbolAddress((void**)&x1, g_x1);
    cudaGetSymbolAddress((void**)&h2, g_h2);
    cudaGetSymbolAddress((void**)&gbuf, g_gbuf);
    cudaGetSymbolAddress((void**)&ubuf, g_ubuf);
    cudaGetSymbolAddress((void**)&shb, g_shb);
    cudaGetSymbolAddress((void**)&r0, g_r0);
    cudaGetSymbolAddress((void**)&r1, g_r1);
    cudaGetSymbolAddress((void**)&cnt, g_cnt);
    cudaGetSymbolAddress((void**)&gidx, g_gidx);
    cudaGetSymbolAddress((void**)&gwt, g_gwt);
    cudaGetSymbolAddress((void**)&gslot, g_gslot);

    zero_cnt_kernel<<<1, 32>>>();

    // ---- attention ----
    ln_kernel<<<BTd, 256>>>(x, ln1w, h);

    // qlat = h @ q_proj_d.T   [BT,L]
    gemm_mma<0,true,false><<<dim3(Ld/128, BTd/128), 256>>>(h, q_proj_d, qlat, nullptr, nullptr,
        BTd, Ld, Hd, Hd, Hd, Ld, nullptr, nullptr, nullptr, nullptr);
    // kvlat = h @ kv_proj_d.T
    gemm_mma<0,true,false><<<dim3(Ld/128, BTd/128), 256>>>(h, kv_proj_d, kvlat, nullptr, nullptr,
        BTd, Ld, Hd, Hd, Hd, Ld, nullptr, nullptr, nullptr, nullptr);
    // v = kvlat @ v_proj_u.T   [BT,H]
    gemm_mma<0,true,false><<<dim3(Hd/128, BTd/128), 256>>>(kvlat, v_proj_u, v, nullptr, nullptr,
        BTd, Hd, Ld, Ld, Ld, Hd, nullptr, nullptr, nullptr, nullptr);
    // q_r = qlat @ rope_q.T
    gemm_mma<0,true,false><<<dim3(Hd/128, BTd/128), 256>>>(qlat, rope_q, q, nullptr, nullptr,
        BTd, Hd, Ld, Ld, Ld, Hd, nullptr, nullptr, nullptr, nullptr);
    // k_r = h @ rope_k.T
    gemm_mma<0,true,false><<<dim3(Hd/128, BTd/128), 256>>>(h, rope_k, k, nullptr, nullptr,
        BTd, Hd, Hd, Hd, Hd, Hd, nullptr, nullptr, nullptr, nullptr);

    rope_kernel<<<BTd, 256>>>(q, k);

    for (int b = 0; b < Bd; b++) {
        gemm_mma<5,true,false><<<dim3(Td/128, Td/128), 256>>>(
            q + (size_t)b*Td*Hd, k + (size_t)b*Td*Hd, scores + (size_t)b*Td*Td,
            nullptr, nullptr, Td, Td, Hd, Hd, Hd, Td, nullptr, nullptr, nullptr, nullptr);
    }
    softmax_kernel<<<dim3(Td, Bd), 256>>>(scores);
    for (int b = 0; b < Bd; b++) {
        gemm_mma<0,false,false><<<dim3(Hd/128, Td/128), 256>>>(
            scores + (size_t)b*Td*Td, v + (size_t)b*Td*Hd, y + (size_t)b*Td*Hd,
            nullptr, nullptr, Td, Hd, Td, Td, Hd, Hd, nullptr, nullptr, nullptr, nullptr);
    }
    // x1 = x + y @ o_proj.T
    gemm_mma<3,true,false><<<dim3(Hd/128, BTd/128), 256>>>(y, o_proj, x1, nullptr, x,
        BTd, Hd, Hd, Hd, Hd, Hd, nullptr, nullptr, nullptr, nullptr);

    // ---- MoE ----
    ln_kernel<<<BTd, 256>>>(x1, ln2w, h2);
    router_kernel<<<BTd, 256>>>(h2, router_w, router_b);

    // shared expert
    gemm_mma<1,true,false><<<dim3(Fd/128, BTd/128), 256>>>(h2, sh_gate, gbuf, nullptr, nullptr,
        BTd, Fd, Hd, Hd, Hd, Fd, nullptr, nullptr, nullptr, nullptr);
    gemm_mma<2,true,false><<<dim3(Fd/128, BTd/128), 256>>>(h2, sh_up, ubuf, nullptr, gbuf,
        BTd, Fd, Hd, Hd, Hd, Fd, nullptr, nullptr, nullptr, nullptr);
    gemm_mma<0,true,false><<<dim3(Hd/128, BTd/128), 256>>>(ubuf, sh_down, shb, nullptr, nullptr,
        BTd, Hd, Fd, Fd, Fd, Hd, nullptr, nullptr, nullptr, nullptr);

    // routed experts (gathered top-2)
    for (int e = 0; e < Ed; e++) {
        const float* wg = ex_gate + (size_t)e * Fd * Hd;
        const float* wu = ex_up   + (size_t)e * Fd * Hd;
        const float* wd = ex_down + (size_t)e * Hd * Fd;
        gemm_mma<1,true,true><<<dim3(Fd/128, BTd/128), 256>>>(h2, wg, gbuf, nullptr, nullptr,
            BTd, Fd, Hd, Hd, Hd, Fd, cnt + e, gidx + e*BTd, nullptr, nullptr);
        gemm_mma<2,true,true><<<dim3(Fd/128, BTd/128), 256>>>(h2, wu, ubuf, nullptr, gbuf,
            BTd, Fd, Hd, Hd, Hd, Fd, cnt + e, gidx + e*BTd, nullptr, nullptr);
        gemm_mma<4,true,false><<<dim3(Hd/128, BTd/128), 256>>>(ubuf, wd, r0, r1, nullptr,
            BTd, Hd, Fd, Fd, Fd, Hd, cnt + e, gidx + e*BTd, gwt + e*BTd, gslot + e*BTd);
    }

    final_add_kernel<<<(BTd * Hd) / 256, 256>>>(x1, shb, r0, r1, out);
}

// round 4
// speedup vs baseline: 3.1754x; 1.2966x over previous
#include <cuda_runtime.h>
#include <math.h>

#define Bd 2
#define Td 2048
#define Hd 1024
#define Ld 256
#define Fd 2048
#define Ed 7
#define BTd (Bd*Td)

// ---------------- scratch (device globals; no allocation) ----------------
__device__ float g_h[BTd*Hd];
__device__ float g_kvlat[BTd*Ld];
__device__ float g_qlat[BTd*Ld];
__device__ float g_v[BTd*Hd];
__device__ float g_q[BTd*Hd];
__device__ float g_k[BTd*Hd];
__device__ float g_scores[(size_t)Bd*Td*Td];
__device__ float g_y[BTd*Hd];
__device__ float g_x1[BTd*Hd];
__device__ float g_h2[BTd*Hd];
__device__ float g_gbuf[(size_t)8*BTd*Fd];   // per-expert slices (7 routed + 1 shared)
__device__ float g_shb[BTd*Hd];
__device__ float g_r0[BTd*Hd];
__device__ float g_r1[BTd*Hd];
__device__ int   g_cnt[Ed];
__device__ int   g_gidx[Ed*BTd];
__device__ float g_gwt[Ed*BTd];
__device__ int   g_gslot[Ed*BTd];

// ---------------- block reduce ----------------
template<bool DOMAX>
__device__ __forceinline__ float blockReduce(float v) {
    __shared__ float sh[8];
    __shared__ float res;
    int lane = threadIdx.x & 31, w = threadIdx.x >> 5;
    #pragma unroll
    for (int o = 16; o; o >>= 1) {
        float t = __shfl_xor_sync(0xffffffffu, v, o);
        v = DOMAX ? fmaxf(v, t) : v + t;
    }
    if (lane == 0) sh[w] = v;
    __syncthreads();
    if (w == 0) {
        v = (lane < (int)(blockDim.x >> 5)) ? sh[lane] : (DOMAX ? -3.4e38f : 0.f);
        #pragma unroll
        for (int o = 4; o; o >>= 1) {
            float t = __shfl_xor_sync(0xffffffffu, v, o);
            v = DOMAX ? fmaxf(v, t) : v + t;
        }
        if (lane == 0) res = v;
    }
    __syncthreads();
    return res;
}

// ---------------- layernorm ----------------
__global__ void ln_kernel(const float* __restrict__ x, const float* __restrict__ w,
                          float* __restrict__ out) {
    int row = blockIdx.x;
    const float* xr = x + (size_t)row * Hd;
    int t = threadIdx.x;
    float v[4];
    float s = 0.f;
    #pragma unroll
    for (int i = 0; i < 4; i++) { v[i] = xr[t + 256*i]; s += v[i]; }
    s = blockReduce<false>(s);
    float mu = s * (1.f / Hd);
    float q = 0.f;
    #pragma unroll
    for (int i = 0; i < 4; i++) { float d = v[i] - mu; q += d * d; }
    q = blockReduce<false>(q);
    float rs = rsqrtf(q * (1.f / Hd) + 1e-5f);
    float* o = out + (size_t)row * Hd;
    #pragma unroll
    for (int i = 0; i < 4; i++) o[t + 256*i] = (v[i] - mu) * rs * w[t + 256*i];
}

// ---------------- rope ----------------
__global__ void rope_kernel(float* __restrict__ q, float* __restrict__ k) {
    int row = blockIdx.x;
    int t = row % Td;
    size_t base = (size_t)row * Hd;
    #pragma unroll
    for (int it = 0; it < 2; it++) {
        int p = threadIdx.x + 256 * it;   // 0..511
        double invf = exp(-(double)(2 * p) / 1024.0 * 9.210340371976184);
        float f = (float)t * (float)invf;
        float c = cosf(f), s = sinf(f);
        float q1 = q[base + p], q2 = q[base + p + 512];
        q[base + p]       = q1 * c - q2 * s;
        q[base + p + 512] = q2 * c + q1 * s;
        float k1 = k[base + p], k2 = k[base + p + 512];
        k[base + p]       = k1 * c - k2 * s;
        k[base + p + 512] = k2 * c + k1 * s;
    }
}

// ---------------- softmax (causal) ----------------
__global__ void softmax_kernel(float* __restrict__ sc) {
    int b = blockIdx.y, i = blockIdx.x;
    float* row = sc + ((size_t)b * Td + i) * Td;
    int t = threadIdx.x;
    int n = i + 1;
    float mx = -3.4e38f;
    for (int j = t; j < n; j += 256) mx = fmaxf(mx, row[j]);
    mx = blockReduce<true>(mx);
    float s = 0.f;
    for (int j = t; j < n; j += 256) s += expf(row[j] - mx);
    s = blockReduce<false>(s);
    float inv = 1.f / s;
    for (int j = t; j < Td; j += 256)
        row[j] = (j < n) ? expf(row[j] - mx) * inv : 0.f;
}

// ---------------- router + top2 gather lists ----------------
__global__ void zero_cnt_kernel() {
    if (threadIdx.x < Ed) g_cnt[threadIdx.x] = 0;
}

__global__ void router_kernel(const float* __restrict__ h2, const float* __restrict__ rw,
                              const float* __restrict__ rb) {
    int m = blockIdx.x;
    int w = threadIdx.x >> 5, lane = threadIdx.x & 31;
    __shared__ float probs[Ed];
    if (w < Ed) {
        const float* hv = h2 + (size_t)m * Hd;
        const float* wv = rw + (size_t)w * Hd;
        float s = 0.f;
        for (int j = lane; j < Hd; j += 32) s += hv[j] * wv[j];
        #pragma unroll
        for (int o = 16; o; o >>= 1) s += __shfl_xor_sync(0xffffffffu, s, o);
        if (lane == 0) probs[w] = 1.f / (1.f + expf(-(s + rb[w])));
    }
    __syncthreads();
    if (threadIdx.x == 0) {
        int e0 = 0; float p0 = probs[0];
        for (int e = 1; e < Ed; e++) if (probs[e] > p0) { p0 = probs[e]; e0 = e; }
        int e1 = -1; float p1 = -3.4e38f;
        for (int e = 0; e < Ed; e++) if (e != e0 && probs[e] > p1) { p1 = probs[e]; e1 = e; }
        int pos = atomicAdd(&g_cnt[e0], 1);
        g_gidx[e0*BTd + pos] = m; g_gwt[e0*BTd + pos] = p0; g_gslot[e0*BTd + pos] = 0;
        pos = atomicAdd(&g_cnt[e1], 1);
        g_gidx[e1*BTd + pos] = m; g_gwt[e1*BTd + pos] = p1; g_gslot[e1*BTd + pos] = 1;
    }
}

// ---------------- tf32 helpers ----------------
__device__ __forceinline__ unsigned f2tf(float f) {
    unsigned u;
    asm("cvt.rna.tf32.f32 %0, %1;" : "=r"(u) : "f"(f));
    return u;
}

__device__ __forceinline__ void mma_tf32(float* d, const unsigned* a, const unsigned* b) {
    asm volatile(
        "mma.sync.aligned.m16n8k8.row.col.f32.tf32.tf32.f32 "
        "{%0,%1,%2,%3}, {%4,%5,%6,%7}, {%8,%9}, {%0,%1,%2,%3};"
        : "+f"(d[0]), "+f"(d[1]), "+f"(d[2]), "+f"(d[3])
        : "r"(a[0]), "r"(a[1]), "r"(a[2]), "r"(a[3]), "r"(b[0]), "r"(b[1]));
}

// per-z pointer tables for batched launches
struct GA {
    const float* A[8];
    const float* B[8];
    float*       C[8];
    const float* aux[8];
    float* r0; float* r1;
    int M, N, K, lda, ldb, ldc;
    const int* gcnt; const int* gidx; const float* gwt; const int* gslot;
};

// ---------------- tensor-core GEMM, 128x128 tile, KT=16, double-buffered ----
// Smem layout: per row (128 rows), 16 k-slots permuted so (k, k+4) within a
// k8 group are adjacent (-> LDS.64 fragments), XOR-swizzled by row for banks.
// Logical k -> slot: g = k>>3, slot = g*8 + 2*(k&3) + ((k&7)>>2), then
// slot ^= (row&7)<<1 per-row swizzle.
// MODE 0: C=v  1: silu  2: C=v*aux (in-place safe)  3: C=v+aux
//      4: scatter w*v to (r0|r1)[gidx]   5: C=v/32, causal tile skip
template<int MODE, bool BTRANS, bool GATHER>
__global__ void __launch_bounds__(256) gemm2(GA ga) {
    const int z = blockIdx.z;
    const int bm = blockIdx.y * 128;
    const int bn = blockIdx.x * 128;
    if (MODE == 5 && bn > bm + 127) return;

    int Meff = ga.M;
    const int* gidx = nullptr; const float* gwt = nullptr; const int* gslot = nullptr;
    if (GATHER || MODE == 4) {
        Meff = ga.gcnt[z];
        gidx = ga.gidx + z * BTd;
        gwt  = ga.gwt  + z * BTd;
        gslot= ga.gslot+ z * BTd;
    }
    if (bm >= Meff) return;

    const float* __restrict__ A   = ga.A[z];
    const float* __restrict__ Bm  = ga.B[z];
    float* __restrict__ C         = ga.C[z];
    const float* __restrict__ aux = ga.aux[z];
    const int K = ga.K, lda = ga.lda, ldb = ga.ldb, ldc = ga.ldc;

    __shared__ unsigned As[2][2048];
    __shared__ unsigned Bs[2][2048];

    const int tid = threadIdx.x;
    const int lane = tid & 31, wid = tid >> 5;
    const int wm = wid & 1, wn = wid >> 1;
    const int gid = lane >> 2, tig = lane & 3;

    // A loader: 2 threads/row, 8 k each (one k8 group)
    const int arow = tid >> 1;
    const int ag = tid & 1;
    const int am = bm + arow;
    const bool aval = am < Meff;
    int asrc = 0;
    if (aval) asrc = GATHER ? gidx[am] : am;
    const float* Ap = A + (size_t)asrc * lda + ag * 8;

    // B loader
    const float* Bp;
    int brow = 0, bg = 0, bk = 0, bn8 = 0;
    if (BTRANS) {
        brow = tid >> 1; bg = tid & 1;
        Bp = Bm + (size_t)(bn + brow) * ldb + bg * 8;
    } else {
        bk = tid >> 4; bn8 = (tid & 15) * 8;
        Bp = Bm + (size_t)bk * ldb + bn + bn8;
    }

    float acc[4][4][4];
    #pragma unroll
    for (int i = 0; i < 4; i++)
        #pragma unroll
        for (int j = 0; j < 4; j++)
            #pragma unroll
            for (int l = 0; l < 4; l++) acc[i][j][l] = 0.f;

    const float4 Z4 = make_float4(0.f, 0.f, 0.f, 0.f);
    float ra[8], rb[8];

    auto load_t = [&](int kt_) {
        *(float4*)ra     = aval ? *(const float4*)(Ap + kt_)     : Z4;
        *(float4*)(ra+4) = aval ? *(const float4*)(Ap + kt_ + 4) : Z4;
        if (BTRANS) {
            *(float4*)rb     = *(const float4*)(Bp + kt_);
            *(float4*)(rb+4) = *(const float4*)(Bp + kt_ + 4);
        } else {
            *(float4*)rb     = *(const float4*)(Bp + (size_t)kt_ * ldb);
            *(float4*)(rb+4) = *(const float4*)(Bp + (size_t)kt_ * ldb + 4);
        }
    };

    auto store_t = [&](int st_) {
        #pragma unroll
        for (int j = 0; j < 4; j++) {
            uint2 u; u.x = f2tf(ra[j]); u.y = f2tf(ra[j+4]);
            int col = (ag*8 + 2*j) ^ ((arow & 7) << 1);
            *(uint2*)&As[st_][arow*16 + col] = u;
        }
        if (BTRANS) {
            #pragma unroll
            for (int j = 0; j < 4; j++) {
                uint2 u; u.x = f2tf(rb[j]); u.y = f2tf(rb[j+4]);
                int col = (bg*8 + 2*j) ^ ((brow & 7) << 1);
                *(uint2*)&Bs[st_][brow*16 + col] = u;
            }
        } else {
            const int g_ = bk >> 3, kk_ = bk & 7;
            const int cb_ = g_*8 + 2*(kk_ & 3) + (kk_ >> 2);
            #pragma unroll
            for (int j = 0; j < 8; j++) {
                int row_ = bn8 + j;
                int col = cb_ ^ ((row_ & 7) << 1);
                Bs[st_][row_*16 + col] = f2tf(rb[j]);
            }
        }
    };

    // prologue: tile0 -> stage0, tile1 -> regs
    load_t(0);
    store_t(0);
    load_t(16);

    int st = 0;
    for (int kt = 0; kt < K; kt += 16) {
        __syncthreads();
        if (kt + 16 < K) {
            store_t(st ^ 1);
            if (kt + 32 < K) load_t(kt + 32);
        }
        // compute stage st: two k8 steps
        #pragma unroll
        for (int g8 = 0; g8 < 2; g8++) {
            uint2 af0[4], af1[4], bf[4];
            const int cfrag = (g8*8 + 2*tig) ^ (gid << 1);
            #pragma unroll
            for (int mt = 0; mt < 4; mt++) {
                int r = wm*64 + mt*16 + gid;
                af0[mt] = *(const uint2*)&As[st][r*16 + cfrag];
                af1[mt] = *(const uint2*)&As[st][(r+8)*16 + cfrag];
            }
            #pragma unroll
            for (int nt = 0; nt < 4; nt++) {
                int c = wn*32 + nt*8 + gid;
                bf[nt] = *(const uint2*)&Bs[st][c*16 + cfrag];
            }
            #pragma unroll
            for (int mt = 0; mt < 4; mt++) {
                unsigned a[4] = {af0[mt].x, af1[mt].x, af0[mt].y, af1[mt].y};
                #pragma unroll
                for (int nt = 0; nt < 4; nt++) {
                    unsigned b[2] = {bf[nt].x, bf[nt].y};
                    mma_tf32(acc[mt][nt], a, b);
                }
            }
        }
        st ^= 1;
    }

    // ---- epilogue ----
    #pragma unroll
    for (int mt = 0; mt < 4; mt++) {
        #pragma unroll
        for (int i2 = 0; i2 < 2; i2++) {
            int gm = bm + wm*64 + mt*16 + gid + i2*8;
            if (gm >= Meff) continue;
            int trow = 0; float wgt = 0.f; float* Ct = C;
            if (MODE == 4) { trow = gidx[gm]; wgt = gwt[gm]; Ct = gslot[gm] ? ga.r1 : ga.r0; }
            #pragma unroll
            for (int nt = 0; nt < 4; nt++) {
                #pragma unroll
                for (int j2 = 0; j2 < 2; j2++) {
                    int gn = bn + wn*32 + nt*8 + tig*2 + j2;
                    float v = acc[mt][nt][i2*2 + j2];
                    size_t o = (size_t)gm * ldc + gn;
                    if (MODE == 0)      C[o] = v;
                    else if (MODE == 1) C[o] = v / (1.f + expf(-v));
                    else if (MODE == 2) C[o] = v * aux[o];
                    else if (MODE == 3) C[o] = v + aux[o];
                    else if (MODE == 4) Ct[(size_t)trow * ldc + gn] = wgt * v;
                    else if (MODE == 5) C[o] = v * 0.03125f;
                }
            }
        }
    }
}

// ---------------- final add ----------------
__global__ void final_add_kernel(const float* __restrict__ a, const float* __restrict__ b,
                                 const float* __restrict__ c, const float* __restrict__ d,
                                 float* __restrict__ out) {
    size_t i = (size_t)blockIdx.x * blockDim.x + threadIdx.x;
    out[i] = a[i] + b[i] + c[i] + d[i];
}

// ---------------- launch ----------------
extern "C" void kernel_launch(void* const* d_in, const int* in_sizes, int n_in,
                              void* d_out, int out_size) {
    (void)in_sizes; (void)n_in; (void)out_size;
    const float* x         = (const float*)d_in[0];
    const float* ln1w      = (const float*)d_in[1];
    const float* ln2w      = (const float*)d_in[2];
    const float* kv_proj_d = (const float*)d_in[3];
    const float* q_proj_d  = (const float*)d_in[4];
    const float* v_proj_u  = (const float*)d_in[7];
    const float* rope_k    = (const float*)d_in[8];
    const float* rope_q    = (const float*)d_in[9];
    const float* o_proj    = (const float*)d_in[10];
    const float* router_w  = (const float*)d_in[11];
    const float* router_b  = (const float*)d_in[12];
    const float* sh_gate   = (const float*)d_in[13];
    const float* sh_up     = (const float*)d_in[14];
    const float* sh_down   = (const float*)d_in[15];
    const float* ex_gate   = (const float*)d_in[16];
    const float* ex_up     = (const float*)d_in[17];
    const float* ex_down   = (const float*)d_in[18];
    float* out = (float*)d_out;

    float *h,*kvlat,*qlat,*v,*q,*k,*scores,*y,*x1,*h2,*gbuf,*shb,*r0,*r1,*gwt;
    int *cnt,*gidx,*gslot;
    cudaGetSymbolAddress((void**)&h, g_h);
    cudaGetSymbolAddress((void**)&kvlat, g_kvlat);
    cudaGetSymbolAddress((void**)&qlat, g_qlat);
    cudaGetSymbolAddress((void**)&v, g_v);
    cudaGetSymbolAddress((void**)&q, g_q);
    cudaGetSymbolAddress((void**)&k, g_k);
    cudaGetSymbolAddress((void**)&scores, g_scores);
    cudaGetSymbolAddress((void**)&y, g_y);
    cudaGetSymbolAddress((void**)&x1, g_x1);
    cudaGetSymbolAddress((void**)&h2, g_h2);
    cudaGetSymbolAddress((void**)&gbuf, g_gbuf);
    cudaGetSymbolAddress((void**)&shb, g_shb);
    cudaGetSymbolAddress((void**)&r0, g_r0);
    cudaGetSymbolAddress((void**)&r1, g_r1);
    cudaGetSymbolAddress((void**)&cnt, g_cnt);
    cudaGetSymbolAddress((void**)&gidx, g_gidx);
    cudaGetSymbolAddress((void**)&gwt, g_gwt);
    cudaGetSymbolAddress((void**)&gslot, g_gslot);

    const size_t ESL = (size_t)BTd * Fd;   // per-expert gbuf slice

    zero_cnt_kernel<<<1, 32>>>();
    ln_kernel<<<BTd, 256>>>(x, ln1w, h);

    // qlat + kvlat (z=2)
    {
        GA ga = {};
        ga.A[0] = h;        ga.A[1] = h;
        ga.B[0] = q_proj_d; ga.B[1] = kv_proj_d;
        ga.C[0] = qlat;     ga.C[1] = kvlat;
        ga.M = BTd; ga.N = Ld; ga.K = Hd; ga.lda = Hd; ga.ldb = Hd; ga.ldc = Ld;
        gemm2<0,true,false><<<dim3(Ld/128, BTd/128, 2), 256>>>(ga);
    }
    // v + q_r (z=2)
    {
        GA ga = {};
        ga.A[0] = kvlat;    ga.A[1] = qlat;
        ga.B[0] = v_proj_u; ga.B[1] = rope_q;
        ga.C[0] = v;        ga.C[1] = q;
        ga.M = BTd; ga.N = Hd; ga.K = Ld; ga.lda = Ld; ga.ldb = Ld; ga.ldc = Hd;
        gemm2<0,true,false><<<dim3(Hd/128, BTd/128, 2), 256>>>(ga);
    }
    // k_r
    {
        GA ga = {};
        ga.A[0] = h; ga.B[0] = rope_k; ga.C[0] = k;
        ga.M = BTd; ga.N = Hd; ga.K = Hd; ga.lda = Hd; ga.ldb = Hd; ga.ldc = Hd;
        gemm2<0,true,false><<<dim3(Hd/128, BTd/128, 1), 256>>>(ga);
    }

    rope_kernel<<<BTd, 256>>>(q, k);

    // scores (z=2, causal)
    {
        GA ga = {};
        for (int b = 0; b < Bd; b++) {
            ga.A[b] = q + (size_t)b*Td*Hd;
            ga.B[b] = k + (size_t)b*Td*Hd;
            ga.C[b] = scores + (size_t)b*Td*Td;
        }
        ga.M = Td; ga.N = Td; ga.K = Hd; ga.lda = Hd; ga.ldb = Hd; ga.ldc = Td;
        gemm2<5,true,false><<<dim3(Td/128, Td/128, Bd), 256>>>(ga);
    }
    softmax_kernel<<<dim3(Td, Bd), 256>>>(scores);
    // PV (z=2)
    {
        GA ga = {};
        for (int b = 0; b < Bd; b++) {
            ga.A[b] = scores + (size_t)b*Td*Td;
            ga.B[b] = v + (size_t)b*Td*Hd;
            ga.C[b] = y + (size_t)b*Td*Hd;
        }
        ga.M = Td; ga.N = Hd; ga.K = Td; ga.lda = Td; ga.ldb = Hd; ga.ldc = Hd;
        gemm2<0,false,false><<<dim3(Hd/128, Td/128, Bd), 256>>>(ga);
    }
    // x1 = x + y @ o_proj.T
    {
        GA ga = {};
        ga.A[0] = y; ga.B[0] = o_proj; ga.C[0] = x1; ga.aux[0] = x;
        ga.M = BTd; ga.N = Hd; ga.K = Hd; ga.lda = Hd; ga.ldb = Hd; ga.ldc = Hd;
        gemm2<3,true,false><<<dim3(Hd/128, BTd/128, 1), 256>>>(ga);
    }

    // ---- MoE ----
    ln_kernel<<<BTd, 256>>>(x1, ln2w, h2);
    router_kernel<<<BTd, 256>>>(h2, router_w, router_b);

    float* shg = gbuf + (size_t)7 * ESL;   // shared-expert slice
    // shared gate (silu)
    {
        GA ga = {};
        ga.A[0] = h2; ga.B[0] = sh_gate; ga.C[0] = shg;
        ga.M = BTd; ga.N = Fd; ga.K = Hd; ga.lda = Hd; ga.ldb = Hd; ga.ldc = Fd;
        gemm2<1,true,false><<<dim3(Fd/128, BTd/128, 1), 256>>>(ga);
    }
    // shared up (in-place multiply into shg)
    {
        GA ga = {};
        ga.A[0] = h2; ga.B[0] = sh_up; ga.C[0] = shg; ga.aux[0] = shg;
        ga.M = BTd; ga.N = Fd; ga.K = Hd; ga.lda = Hd; ga.ldb = Hd; ga.ldc = Fd;
        gemm2<2,true,false><<<dim3(Fd/128, BTd/128, 1), 256>>>(ga);
    }
    // shared down
    {
        GA ga = {};
        ga.A[0] = shg; ga.B[0] = sh_down; ga.C[0] = shb;
        ga.M = BTd; ga.N = Hd; ga.K = Fd; ga.lda = Fd; ga.ldb = Fd; ga.ldc = Hd;
        gemm2<0,true,false><<<dim3(Hd/128, BTd/128, 1), 256>>>(ga);
    }

    // routed experts, all 7 batched per stage
    {
        GA ga = {};
        for (int e = 0; e < Ed; e++) {
            ga.A[e] = h2;
            ga.B[e] = ex_gate + (size_t)e * Fd * Hd;
            ga.C[e] = gbuf + (size_t)e * ESL;
        }
        ga.M = BTd; ga.N = Fd; ga.K = Hd; ga.lda = Hd; ga.ldb = Hd; ga.ldc = Fd;
        ga.gcnt = cnt; ga.gidx = gidx; ga.gwt = gwt; ga.gslot = gslot;
        gemm2<1,true,true><<<dim3(Fd/128, BTd/128, Ed), 256>>>(ga);
    }
    {
        GA ga = {};
        for (int e = 0; e < Ed; e++) {
            ga.A[e] = h2;
            ga.B[e] = ex_up + (size_t)e * Fd * Hd;
            ga.C[e] = gbuf + (size_t)e * ESL;
            ga.aux[e] = gbuf + (size_t)e * ESL;
        }
        ga.M = BTd; ga.N = Fd; ga.K = Hd; ga.lda = Hd; ga.ldb = Hd; ga.ldc = Fd;
        ga.gcnt = cnt; ga.gidx = gidx; ga.gwt = gwt; ga.gslot = gslot;
        gemm2<2,true,true><<<dim3(Fd/128, BTd/128, Ed), 256>>>(ga);
    }
    {
        GA ga = {};
        for (int e = 0; e < Ed; e++) {
            ga.A[e] = gbuf + (size_t)e * ESL;
            ga.B[e] = ex_down + (size_t)e * Hd * Fd;
        }
        ga.r0 = r0; ga.r1 = r1;
        ga.M = BTd; ga.N = Hd; ga.K = Fd; ga.lda = Fd; ga.ldb = Fd; ga.ldc = Hd;
        ga.gcnt = cnt; ga.gidx = gidx; ga.gwt = gwt; ga.gslot = gslot;
        gemm2<4,true,false><<<dim3(Hd/128, BTd/128, Ed), 256>>>(ga);
    }

    final_add_kernel<<<(BTd * Hd) / 256, 256>>>(x1, shb, r0, r1, out);
}